// round 9
// baseline (speedup 1.0000x reference)
#include <cuda_runtime.h>
#include <cuda_bf16.h>

#define R   2
#define TX  32
#define TY  4
#define TZ  2
#define SXT (TX + 2*R)   // 36
#define SYT (TY + 2*R)   // 8
#define SZT (TZ + 2*R)   // 6
#define NDIM 128
#define NVOX (NDIM*NDIM*NDIM)
#define NTHREADS (TX*TY*TZ)   // 256

using u64 = unsigned long long;
using u32 = unsigned int;

__device__ __forceinline__ u64 pk2(float lo, float hi) {
    u64 r; asm("mov.b64 %0, {%1, %2};" : "=l"(r) : "f"(lo), "f"(hi)); return r;
}
__device__ __forceinline__ void upk2(u64 v, float& lo, float& hi) {
    asm("mov.b64 {%0, %1}, %2;" : "=f"(lo), "=f"(hi) : "l"(v));
}
__device__ __forceinline__ u64 fma2(u64 a, u64 b, u64 c) {
    u64 d; asm("fma.rn.f32x2 %0, %1, %2, %3;" : "=l"(d) : "l"(a), "l"(b), "l"(c)); return d;
}
__device__ __forceinline__ u64 add2(u64 a, u64 b) {
    u64 d; asm("add.rn.f32x2 %0, %1, %2;" : "=l"(d) : "l"(a), "l"(b)); return d;
}

// ---- MUFU tap: bf16x2 ex2 (costs 16 MUFU cycles per packed tap) ----
__device__ __forceinline__ void tapM(u64 y2, u64 negone2, u64 twoyc2, u64 bb2,
                                     u64& num2, u64& den2)
{
    u64 t = fma2(y2, negone2, twoyc2);   // 2yc - y
    u64 a = fma2(y2, t, bb2);            // y(2yc-y) + (b - yc^2) = b - (y-yc)^2
    float alo, ahi; upk2(a, alo, ahi);
    u32 abl = __float_as_uint(alo);
    u32 abh = __float_as_uint(ahi);
    u32 h2;
    asm("prmt.b32 %0, %1, %2, 0x7632;" : "=r"(h2) : "r"(abl), "r"(abh));
    asm("ex2.approx.ftz.bf16x2 %0, %0;" : "+r"(h2));
    u32 wlo_b = h2 << 16;
    u32 whi_b = h2 & 0xFFFF0000u;
    u64 w2 = pk2(__uint_as_float(wlo_b), __uint_as_float(whi_b));
    num2 = fma2(w2, y2, num2);
    den2 = add2(den2, w2);
}

// ---- Poly tap: 2^arg on the FMA pipe, zero MUFU ----
// magic-add range reduction + degree-3 2^f + integer exponent insert.
__device__ __forceinline__ void tapP(u64 y2, u64 negone2, u64 twoyc2, u64 bb2,
                                     u64 one2, u64 magic2, u64 nmagic2,
                                     u64 c3_2, u64 c2_2, u64 c1_2, u64 c0_2,
                                     u64& num2, u64& den2)
{
    u64 t = fma2(y2, negone2, twoyc2);
    u64 a = fma2(y2, t, bb2);            // arg <= 0 always (incl. sentinel -> -2.9e36)
    float alo, ahi; upk2(a, alo, ahi);
    float aal = fmaxf(alo, -120.0f);     // clamp: sentinel -> w = 2^-120 ~ exact 0
    float aah = fmaxf(ahi, -120.0f);
    u64 aa2 = pk2(aal, aah);
    u64 v2 = fma2(aa2, one2, magic2);    // magic = 1.5*2^23: v = magic + round(aa), ulp=1
    u64 g2 = fma2(v2, one2, nmagic2);    // round(aa)
    u64 f2 = fma2(g2, negone2, aa2);     // f = aa - round(aa) in [-0.5, 0.5]
    u64 p2 = fma2(c3_2, f2, c2_2);       // degree-3 2^f, rel err ~8e-5
    p2 = fma2(p2, f2, c1_2);
    p2 = fma2(p2, f2, c0_2);
    float vlo, vhi, plo, phi;
    upk2(v2, vlo, vhi);
    upk2(p2, plo, phi);
    // w = p * 2^i : v_bits = 0x4B400000 + i, and 0x4B400000<<23 == 0 mod 2^32,
    // so (v_bits<<23) == i<<23 exactly. Pure ALU exponent insert.
    u32 wlo_b = __float_as_uint(plo) + (__float_as_uint(vlo) << 23);
    u32 whi_b = __float_as_uint(phi) + (__float_as_uint(vhi) << 23);
    u64 w2 = pk2(__uint_as_float(wlo_b), __uint_as_float(whi_b));
    num2 = fma2(w2, y2, num2);
    den2 = add2(den2, w2);
}

__global__ __launch_bounds__(NTHREADS, 4)   // <=64 regs, no spills
void bilateral3d_kernel(const float* __restrict__ in,
                        float* __restrict__ out,
                        const float* __restrict__ p_sx,
                        const float* __restrict__ p_sy,
                        const float* __restrict__ p_sz,
                        const float* __restrict__ p_cs)
{
    __shared__ float2 tile[SZT][SYT][SXT];   // 13824 B, holds y = s*x per lane

    const float LOG2E = 1.4426950408889634f;
    const float sx = *p_sx, sy = *p_sy, sz = *p_sz, cs = *p_cs;
    const float ax = -LOG2E / (2.0f * sx * sx);
    const float ay = -LOG2E / (2.0f * sy * sy);
    const float az = -LOG2E / (2.0f * sz * sz);
    const float s  = sqrtf(LOG2E / (2.0f * cs * cs));

    const int x0 = blockIdx.x * TX;
    const int y0 = blockIdx.y * TY;
    const int z0 = blockIdx.z * TZ;

    // ---- cooperative tile load (pre-scaled by s), sentinel halo ----
    const float BIG = 1e18f;
    const int tid = threadIdx.x + TX * (threadIdx.y + TY * threadIdx.z);
    float2* tflat = &tile[0][0][0];
    for (int i = tid; i < SZT*SYT*SXT; i += NTHREADS) {
        int lxx = i % SXT;
        int t   = i / SXT;
        int lyy = t % SYT;
        int lzz = t / SYT;
        int gx = x0 + lxx - R;
        int gy = y0 + lyy - R;
        int gz = z0 + lzz - R;
        float2 v = make_float2(BIG, BIG);
        if ((unsigned)gx < NDIM && (unsigned)gy < NDIM && (unsigned)gz < NDIM) {
            size_t g = ((size_t)gz * NDIM + gy) * NDIM + gx;
            v.x = in[g] * s;
            v.y = in[g + NVOX] * s;
        }
        tflat[i] = v;
    }
    __syncthreads();

    const float ax1 = ax, ax4 = 4.0f * ax;
    float wy[5];
    #pragma unroll
    for (int i = 0; i < 5; i++) {
        float d = (float)(i - R);
        wy[i] = d * d * ay;
    }

    const int lx = threadIdx.x, ly = threadIdx.y, lz = threadIdx.z;
    const float2 yc2 = tile[lz + R][ly + R][lx + R];   // s*xc per lane
    const float ycsq_lo = yc2.x * yc2.x;
    const float ycsq_hi = yc2.y * yc2.y;
    const u64 negone2 = pk2(-1.0f, -1.0f);
    const u64 twoyc2  = pk2(2.0f * yc2.x, 2.0f * yc2.y);

    // poly constants (packed)
    const float MAGIC = 12582912.0f;     // 1.5 * 2^23
    const u64 one2    = pk2(1.0f, 1.0f);
    const u64 magic2  = pk2(MAGIC, MAGIC);
    const u64 nmagic2 = pk2(-MAGIC, -MAGIC);
    const u64 c3_2 = pk2(0.0555041f, 0.0555041f);
    const u64 c2_2 = pk2(0.2426310f, 0.2426310f);
    const u64 c1_2 = pk2(0.6931472f, 0.6931472f);
    const u64 c0_2 = pk2(0.9999250f, 0.9999250f);

    u64 num2 = pk2(0.0f, 0.0f);
    u64 den2 = pk2(0.0f, 0.0f);

    #define TAP_M(r_, bb_) tapM(r_, negone2, twoyc2, bb_, num2, den2)
    #define TAP_P(r_, bb_) tapP(r_, negone2, twoyc2, bb_, one2, magic2, nmagic2, \
                                 c3_2, c2_2, c1_2, c0_2, num2, den2)

    #pragma unroll 1
    for (int dz = 0; dz < 5; dz++) {
        float dzf = (float)(dz - R);
        float wzv = dzf * dzf * az;
        #pragma unroll
        for (int dy = 0; dy < 5; dy++) {
            const float b0 = wy[dy] + wzv;
            const float b1 = b0 + ax1;
            const float b4 = b0 + ax4;
            const u64 bb0 = pk2(b0 - ycsq_lo, b0 - ycsq_hi);  // b - yc^2 per lane
            const u64 bb1 = pk2(b1 - ycsq_lo, b1 - ycsq_hi);
            const u64 bb4 = pk2(b4 - ycsq_lo, b4 - ycsq_hi);
            const u64* row = reinterpret_cast<const u64*>(&tile[lz + dz][ly + dy][lx]);
            u64 r0 = row[0], r1 = row[1], r2 = row[2], r3 = row[3], r4 = row[4];
            // r = 7/25 poly: dx=2 every row; dx=1,3 also on the dy==2 row.
            TAP_M(r0, bb4);
            if (dy == 2) { TAP_P(r1, bb1); } else { TAP_M(r1, bb1); }
            TAP_P(r2, bb0);
            if (dy == 2) { TAP_P(r3, bb1); } else { TAP_M(r3, bb1); }
            TAP_M(r4, bb4);
        }
    }
    #undef TAP_M
    #undef TAP_P

    float nlo, nhi, dlo, dhi;
    upk2(num2, nlo, nhi);
    upk2(den2, dlo, dhi);

    const float inv_s = __fdividef(1.0f, s);
    const size_t o = ((size_t)(z0 + lz) * NDIM + (y0 + ly)) * NDIM + (x0 + lx);
    out[o]        = __fdividef(nlo, dlo) * inv_s;
    out[o + NVOX] = __fdividef(nhi, dhi) * inv_s;
}

extern "C" void kernel_launch(void* const* d_in, const int* in_sizes, int n_in,
                              void* d_out, int out_size)
{
    const float* img = (const float*)d_in[0];
    const float* psx = (const float*)d_in[1];
    const float* psy = (const float*)d_in[2];
    const float* psz = (const float*)d_in[3];
    const float* pcs = (const float*)d_in[4];
    float* outp = (float*)d_out;

    dim3 block(TX, TY, TZ);
    dim3 grid(NDIM / TX, NDIM / TY, NDIM / TZ);
    bilateral3d_kernel<<<grid, block>>>(img, outp, psx, psy, psz, pcs);
}

// round 10
// speedup vs baseline: 1.0052x; 1.0052x over previous
#include <cuda_runtime.h>
#include <cuda_bf16.h>

#define R   2
#define TX  32
#define TY  4
#define TZ  2
#define SXT (TX + 2*R)   // 36
#define SYT (TY + 2*R)   // 8
#define SZT (TZ + 2*R)   // 6
#define NDIM 128
#define NVOX (NDIM*NDIM*NDIM)
#define NTHREADS (TX*TY*TZ)   // 256

using u64 = unsigned long long;
using u32 = unsigned int;

__device__ __forceinline__ u64 pk2(float lo, float hi) {
    u64 r; asm("mov.b64 %0, {%1, %2};" : "=l"(r) : "f"(lo), "f"(hi)); return r;
}
__device__ __forceinline__ void upk2(u64 v, float& lo, float& hi) {
    asm("mov.b64 {%0, %1}, %2;" : "=f"(lo), "=f"(hi) : "l"(v));
}
__device__ __forceinline__ u64 fma2(u64 a, u64 b, u64 c) {
    u64 d; asm("fma.rn.f32x2 %0, %1, %2, %3;" : "=l"(d) : "l"(a), "l"(b), "l"(c)); return d;
}
__device__ __forceinline__ u64 add2(u64 a, u64 b) {
    u64 d; asm("add.rn.f32x2 %0, %1, %2;" : "=l"(d) : "l"(a), "l"(b)); return d;
}
__device__ __forceinline__ u64 sub2(u64 a, u64 b) {
    u64 d; asm("sub.rn.f32x2 %0, %1, %2;" : "=l"(d) : "l"(a), "l"(b)); return d;
}

// ---- MUFU tap: bf16x2 ex2 (16 MUFU cyc per packed tap) ----
__device__ __forceinline__ void tapM(u64 y2, u64 twoyc2, u64 bb2,
                                     u64& num2, u64& den2)
{
    u64 t = sub2(twoyc2, y2);            // 2yc - y
    u64 a = fma2(y2, t, bb2);            // b - (y-yc)^2  (log2 of weight)
    float alo, ahi; upk2(a, alo, ahi);
    u32 abl = __float_as_uint(alo);
    u32 abh = __float_as_uint(ahi);
    u32 h2;
    asm("prmt.b32 %0, %1, %2, 0x7632;" : "=r"(h2) : "r"(abl), "r"(abh));
    asm("ex2.approx.ftz.bf16x2 %0, %0;" : "+r"(h2));
    u32 wlo_b = h2 << 16;
    u32 whi_b = h2 & 0xFFFF0000u;
    u64 w2 = pk2(__uint_as_float(wlo_b), __uint_as_float(whi_b));
    num2 = fma2(w2, y2, num2);
    den2 = add2(den2, w2);
}

// ---- Poly tap: 2^arg entirely on FMA/ALU pipes, zero MUFU ----
__device__ __forceinline__ void tapP(u64 y2, u64 twoyc2, u64 bb2,
                                     u64 magic2, u64 nmagic2,
                                     u64 c3_2, u64 c2_2, u64 c1_2, u64 c0_2,
                                     u64& num2, u64& den2)
{
    u64 t = sub2(twoyc2, y2);
    u64 a = fma2(y2, t, bb2);            // arg <= 0 (sentinel -> -1.4e36)
    float alo, ahi; upk2(a, alo, ahi);
    float aal = fmaxf(alo, -120.0f);     // clamp: sentinel -> w = 2^-120 ~ 0
    float aah = fmaxf(ahi, -120.0f);
    u64 aa2 = pk2(aal, aah);
    u64 v2 = add2(aa2, magic2);          // magic=1.5*2^23: v_bits = magic_bits + round(aa)
    u64 g2 = add2(v2, nmagic2);          // round(aa), exact
    u64 f2 = sub2(aa2, g2);              // f in [-0.5, 0.5]
    u64 p2 = fma2(c3_2, f2, c2_2);       // degree-3 2^f
    p2 = fma2(p2, f2, c1_2);
    p2 = fma2(p2, f2, c0_2);
    float vlo, vhi, plo, phi;
    upk2(v2, vlo, vhi);
    upk2(p2, plo, phi);
    // (magic_bits<<23) == 0 mod 2^32, so (v_bits<<23) inserts exactly i into the exponent
    u32 wlo_b = __float_as_uint(plo) + (__float_as_uint(vlo) << 23);
    u32 whi_b = __float_as_uint(phi) + (__float_as_uint(vhi) << 23);
    u64 w2 = pk2(__uint_as_float(wlo_b), __uint_as_float(whi_b));
    num2 = fma2(w2, y2, num2);
    den2 = add2(den2, w2);
}

__global__ __launch_bounds__(NTHREADS, 5)   // 48-reg cap -> 5 CTAs/SM (62.5% occ)
void bilateral3d_kernel(const float* __restrict__ in,
                        float* __restrict__ out,
                        const float* __restrict__ p_sx,
                        const float* __restrict__ p_sy,
                        const float* __restrict__ p_sz,
                        const float* __restrict__ p_cs)
{
    __shared__ float2 tile[SZT][SYT][SXT];   // 13824 B, holds y = s*x per lane

    const float LOG2E = 1.4426950408889634f;
    const float sx = *p_sx, sy = *p_sy, sz = *p_sz, cs = *p_cs;
    const float ax = -LOG2E / (2.0f * sx * sx);
    const float ay = -LOG2E / (2.0f * sy * sy);
    const float az = -LOG2E / (2.0f * sz * sz);
    const float s  = sqrtf(LOG2E / (2.0f * cs * cs));

    const int x0 = blockIdx.x * TX;
    const int y0 = blockIdx.y * TY;
    const int z0 = blockIdx.z * TZ;

    // ---- cooperative tile load (pre-scaled by s), sentinel halo ----
    const float BIG = 1e18f;
    const int tid = threadIdx.x + TX * (threadIdx.y + TY * threadIdx.z);
    float2* tflat = &tile[0][0][0];
    for (int i = tid; i < SZT*SYT*SXT; i += NTHREADS) {
        int lxx = i % SXT;
        int t   = i / SXT;
        int lyy = t % SYT;
        int lzz = t / SYT;
        int gx = x0 + lxx - R;
        int gy = y0 + lyy - R;
        int gz = z0 + lzz - R;
        float2 v = make_float2(BIG, BIG);
        if ((unsigned)gx < NDIM && (unsigned)gy < NDIM && (unsigned)gz < NDIM) {
            size_t g = ((size_t)gz * NDIM + gy) * NDIM + gx;
            v.x = in[g] * s;
            v.y = in[g + NVOX] * s;
        }
        tflat[i] = v;
    }
    __syncthreads();

    const int lx = threadIdx.x, ly = threadIdx.y, lz = threadIdx.z;
    const float2 yc2 = tile[lz + R][ly + R][lx + R];   // s*xc per lane
    const float ycsq_lo = yc2.x * yc2.x;
    const float ycsq_hi = yc2.y * yc2.y;
    const u64 twoyc2 = pk2(2.0f * yc2.x, 2.0f * yc2.y);

    // poly constants (packed)
    const float MAGIC = 12582912.0f;     // 1.5 * 2^23
    const u64 magic2  = pk2(MAGIC, MAGIC);
    const u64 nmagic2 = pk2(-MAGIC, -MAGIC);
    const u64 c3_2 = pk2(0.0555041f, 0.0555041f);
    const u64 c2_2 = pk2(0.2426310f, 0.2426310f);
    const u64 c1_2 = pk2(0.6931472f, 0.6931472f);
    const u64 c0_2 = pk2(0.9999250f, 0.9999250f);

    u64 num2 = pk2(0.0f, 0.0f);
    u64 den2 = pk2(0.0f, 0.0f);

    #define TAP_M(r_, bb_) tapM(r_, twoyc2, bb_, num2, den2)
    #define TAP_P(r_, bb_) tapP(r_, twoyc2, bb_, magic2, nmagic2, \
                                 c3_2, c2_2, c1_2, c0_2, num2, den2)

    #pragma unroll 1
    for (int dz = 0; dz < 5; dz++) {
        float dzf = (float)(dz - R);
        float wzv = dzf * dzf * az;
        #pragma unroll
        for (int dy = 0; dy < 5; dy++) {
            float dyf = (float)(dy - R);
            const float b0 = fmaf(dyf * dyf, ay, wzv);
            const float b1 = b0 + ax;
            const float b4 = b0 + 4.0f * ax;
            const u64 bb0 = pk2(b0 - ycsq_lo, b0 - ycsq_hi);
            const u64 bb1 = pk2(b1 - ycsq_lo, b1 - ycsq_hi);
            const u64 bb4 = pk2(b4 - ycsq_lo, b4 - ycsq_hi);
            const u64* row = reinterpret_cast<const u64*>(&tile[lz + dz][ly + dy][lx]);
            u64 r0 = row[0], r1 = row[1], r2 = row[2], r3 = row[3], r4 = row[4];
            // r = 7/25 poly: dx=2 every row; dx=1,3 additionally on the dy==2 row.
            TAP_M(r0, bb4);
            if (dy == 2) { TAP_P(r1, bb1); } else { TAP_M(r1, bb1); }
            TAP_P(r2, bb0);
            if (dy == 2) { TAP_P(r3, bb1); } else { TAP_M(r3, bb1); }
            TAP_M(r4, bb4);
        }
    }
    #undef TAP_M
    #undef TAP_P

    float nlo, nhi, dlo, dhi;
    upk2(num2, nlo, nhi);
    upk2(den2, dlo, dhi);

    const float inv_s = __fdividef(1.0f, s);
    const size_t o = ((size_t)(z0 + lz) * NDIM + (y0 + ly)) * NDIM + (x0 + lx);
    out[o]        = __fdividef(nlo, dlo) * inv_s;
    out[o + NVOX] = __fdividef(nhi, dhi) * inv_s;
}

extern "C" void kernel_launch(void* const* d_in, const int* in_sizes, int n_in,
                              void* d_out, int out_size)
{
    const float* img = (const float*)d_in[0];
    const float* psx = (const float*)d_in[1];
    const float* psy = (const float*)d_in[2];
    const float* psz = (const float*)d_in[3];
    const float* pcs = (const float*)d_in[4];
    float* outp = (float*)d_out;

    dim3 block(TX, TY, TZ);
    dim3 grid(NDIM / TX, NDIM / TY, NDIM / TZ);
    bilateral3d_kernel<<<grid, block>>>(img, outp, psx, psy, psz, pcs);
}

// round 13
// speedup vs baseline: 1.0681x; 1.0626x over previous
#include <cuda_runtime.h>
#include <cuda_bf16.h>

#define R   2
#define TX  32
#define TY  4
#define TZ  2
#define SXT (TX + 2*R)   // 36
#define SYT (TY + 2*R)   // 8
#define SZT (TZ + 2*R)   // 6
#define NDIM 128
#define NVOX (NDIM*NDIM*NDIM)
#define NTHREADS (TX*TY*TZ)   // 256

using u64 = unsigned long long;
using u32 = unsigned int;

__device__ __forceinline__ u64 pk2(float lo, float hi) {
    u64 r; asm("mov.b64 %0, {%1, %2};" : "=l"(r) : "f"(lo), "f"(hi)); return r;
}
__device__ __forceinline__ void upk2(u64 v, float& lo, float& hi) {
    asm("mov.b64 {%0, %1}, %2;" : "=f"(lo), "=f"(hi) : "l"(v));
}
__device__ __forceinline__ u64 fma2(u64 a, u64 b, u64 c) {
    u64 d; asm("fma.rn.f32x2 %0, %1, %2, %3;" : "=l"(d) : "l"(a), "l"(b), "l"(c)); return d;
}
__device__ __forceinline__ u64 add2(u64 a, u64 b) {
    u64 d; asm("add.rn.f32x2 %0, %1, %2;" : "=l"(d) : "l"(a), "l"(b)); return d;
}
__device__ __forceinline__ u64 sub2(u64 a, u64 b) {
    u64 d; asm("sub.rn.f32x2 %0, %1, %2;" : "=l"(d) : "l"(a), "l"(b)); return d;
}

// ---- MUFU tap: bf16x2 ex2 (rt16 per packed tap) ----
__device__ __forceinline__ void tapM(u64 y2, u64 twoyc2, u64 bb2,
                                     u64& num2, u64& den2)
{
    u64 t = sub2(twoyc2, y2);            // 2yc - y
    u64 a = fma2(y2, t, bb2);            // b - (y-yc)^2
    float alo, ahi; upk2(a, alo, ahi);
    u32 abl = __float_as_uint(alo);
    u32 abh = __float_as_uint(ahi);
    u32 h2;
    asm("prmt.b32 %0, %1, %2, 0x7632;" : "=r"(h2) : "r"(abl), "r"(abh));
    asm("ex2.approx.ftz.bf16x2 %0, %0;" : "+r"(h2));
    u32 wlo_b = h2 << 16;
    u32 whi_b = h2 & 0xFFFF0000u;
    u64 w2 = pk2(__uint_as_float(wlo_b), __uint_as_float(whi_b));
    num2 = fma2(w2, y2, num2);
    den2 = add2(den2, w2);
}

// ---- Poly tap: deg-2 2^arg on FMA/ALU pipes, zero MUFU ----
__device__ __forceinline__ void tapP(u64 y2, u64 twoyc2, u64 bb2,
                                     u64 magic2, u64 nmagic2,
                                     u64 c2_2, u64 c1_2, u64 c0_2,
                                     u64& num2, u64& den2)
{
    u64 t = sub2(twoyc2, y2);
    u64 a = fma2(y2, t, bb2);            // arg <= 0 (sentinel -> ~ -1.4e36)
    float alo, ahi; upk2(a, alo, ahi);
    float aal = fmaxf(alo, -120.0f);     // clamp: sentinel -> w = 2^-120 ~ 0
    float aah = fmaxf(ahi, -120.0f);
    u64 aa2 = pk2(aal, aah);
    u64 v2 = add2(aa2, magic2);          // v_bits = magic_bits + round(aa)
    u64 g2 = add2(v2, nmagic2);          // round(aa), exact
    u64 f2 = sub2(aa2, g2);              // f in [-0.5, 0.5]
    u64 p2 = fma2(c2_2, f2, c1_2);       // degree-2 2^f (economized, ~0.2% rel)
    p2 = fma2(p2, f2, c0_2);
    float vlo, vhi, plo, phi;
    upk2(v2, vlo, vhi);
    upk2(p2, plo, phi);
    // (magic_bits<<23) == 0 mod 2^32 -> (v_bits<<23) inserts i exactly
    u32 wlo_b = __float_as_uint(plo) + (__float_as_uint(vlo) << 23);
    u32 whi_b = __float_as_uint(phi) + (__float_as_uint(vhi) << 23);
    u64 w2 = pk2(__uint_as_float(wlo_b), __uint_as_float(whi_b));
    num2 = fma2(w2, y2, num2);
    den2 = add2(den2, w2);
}

__global__ __launch_bounds__(NTHREADS, 5)   // 48-reg cap, 5 CTAs/SM
void bilateral3d_kernel(const float* __restrict__ in,
                        float* __restrict__ out,
                        const float* __restrict__ p_sx,
                        const float* __restrict__ p_sy,
                        const float* __restrict__ p_sz,
                        const float* __restrict__ p_cs)
{
    __shared__ float2 tile[SZT][SYT][SXT];   // 13824 B, holds y = s*x

    const float LOG2E = 1.4426950408889634f;
    const float sx = *p_sx, sy = *p_sy, sz = *p_sz, cs = *p_cs;
    const float ax = -LOG2E / (2.0f * sx * sx);
    const float ay = -LOG2E / (2.0f * sy * sy);
    const float az = -LOG2E / (2.0f * sz * sz);
    const float s  = sqrtf(LOG2E / (2.0f * cs * cs));

    const int x0 = blockIdx.x * TX;
    const int y0 = blockIdx.y * TY;
    const int z0 = blockIdx.z * TZ;

    // ---- cooperative tile load (pre-scaled by s), sentinel halo ----
    const float BIG = 1e18f;
    const int tid = threadIdx.x + TX * (threadIdx.y + TY * threadIdx.z);
    float2* tflat = &tile[0][0][0];
    for (int i = tid; i < SZT*SYT*SXT; i += NTHREADS) {
        int lxx = i % SXT;
        int t   = i / SXT;
        int lyy = t % SYT;
        int lzz = t / SYT;
        int gx = x0 + lxx - R;
        int gy = y0 + lyy - R;
        int gz = z0 + lzz - R;
        float2 v = make_float2(BIG, BIG);
        if ((unsigned)gx < NDIM && (unsigned)gy < NDIM && (unsigned)gz < NDIM) {
            size_t g = ((size_t)gz * NDIM + gy) * NDIM + gx;
            v.x = in[g] * s;
            v.y = in[g + NVOX] * s;
        }
        tflat[i] = v;
    }
    __syncthreads();

    const int lx = threadIdx.x, ly = threadIdx.y, lz = threadIdx.z;
    const float2 yc2 = tile[lz + R][ly + R][lx + R];   // s*xc
    const float ycsq_lo = yc2.x * yc2.x;
    const float ycsq_hi = yc2.y * yc2.y;
    const u64 twoyc2 = pk2(2.0f * yc2.x, 2.0f * yc2.y);

    // poly constants
    const float MAGIC = 12582912.0f;     // 1.5 * 2^23
    const u64 magic2  = pk2(MAGIC, MAGIC);
    const u64 nmagic2 = pk2(-MAGIC, -MAGIC);
    const u64 c2_2 = pk2(0.2402265f, 0.2402265f);
    const u64 c1_2 = pk2(0.7035500f, 0.7035500f);
    const u64 c0_2 = pk2(0.9991000f, 0.9991000f);

    u64 num2 = pk2(0.0f, 0.0f);
    u64 den2 = pk2(0.0f, 0.0f);

    #define TAP_M(r_, bb_) tapM(r_, twoyc2, bb_, num2, den2)
    #define TAP_P(r_, bb_) tapP(r_, twoyc2, bb_, magic2, nmagic2, \
                                 c2_2, c1_2, c0_2, num2, den2)
    // One poly tap per row at dx==dy: SFU demand is uniform in time.
    #define ROW(row_, dyv_)                                                  \
        {                                                                    \
            u64 r0 = (row_)[0], r1 = (row_)[1], r2 = (row_)[2],              \
                r3 = (row_)[3], r4 = (row_)[4];                              \
            if ((dyv_) == 0) { TAP_P(r0, bb4); } else { TAP_M(r0, bb4); }    \
            if ((dyv_) == 1) { TAP_P(r1, bb1); } else { TAP_M(r1, bb1); }    \
            if ((dyv_) == 2) { TAP_P(r2, bb0); } else { TAP_M(r2, bb0); }    \
            if ((dyv_) == 3) { TAP_P(r3, bb1); } else { TAP_M(r3, bb1); }    \
            if ((dyv_) == 4) { TAP_P(r4, bb4); } else { TAP_M(r4, bb4); }    \
        }

    #pragma unroll 1
    for (int dz = 0; dz < 5; dz++) {
        float dzf = (float)(dz - R);
        float wzv = dzf * dzf * az;
        #pragma unroll
        for (int dy = 0; dy < 5; dy++) {
            float dyf = (float)(dy - R);
            const float b0 = fmaf(dyf * dyf, ay, wzv);
            const float b1 = b0 + ax;
            const float b4 = b0 + 4.0f * ax;
            const u64 bb0 = pk2(b0 - ycsq_lo, b0 - ycsq_hi);
            const u64 bb1 = pk2(b1 - ycsq_lo, b1 - ycsq_hi);
            const u64 bb4 = pk2(b4 - ycsq_lo, b4 - ycsq_hi);
            const u64* row = reinterpret_cast<const u64*>(&tile[lz + dz][ly + dy][lx]);
            ROW(row, dy)
        }
    }
    #undef ROW
    #undef TAP_M
    #undef TAP_P

    float nlo, nhi, dlo, dhi;
    upk2(num2, nlo, nhi);
    upk2(den2, dlo, dhi);

    const float inv_s = __fdividef(1.0f, s);
    const size_t o = ((size_t)(z0 + lz) * NDIM + (y0 + ly)) * NDIM + (x0 + lx);
    out[o]        = __fdividef(nlo, dlo) * inv_s;
    out[o + NVOX] = __fdividef(nhi, dhi) * inv_s;
}

extern "C" void kernel_launch(void* const* d_in, const int* in_sizes, int n_in,
                              void* d_out, int out_size)
{
    const float* img = (const float*)d_in[0];
    const float* psx = (const float*)d_in[1];
    const float* psy = (const float*)d_in[2];
    const float* psz = (const float*)d_in[3];
    const float* pcs = (const float*)d_in[4];
    float* outp = (float*)d_out;

    dim3 block(TX, TY, TZ);
    dim3 grid(NDIM / TX, NDIM / TY, NDIM / TZ);
    bilateral3d_kernel<<<grid, block>>>(img, outp, psx, psy, psz, pcs);
}

// round 14
// speedup vs baseline: 1.1686x; 1.0941x over previous
#include <cuda_runtime.h>
#include <cuda_bf16.h>

#define R   2
#define TX  32
#define TY  4
#define TZ  2
#define SXT (TX + 2*R)   // 36
#define SYT (TY + 2*R)   // 8
#define SZT (TZ + 2*R)   // 6
#define NDIM 128
#define NVOX (NDIM*NDIM*NDIM)
#define NTHREADS (TX*TY*TZ)   // 256

using u64 = unsigned long long;
using u32 = unsigned int;

__device__ __forceinline__ u64 pk2(float lo, float hi) {
    u64 r; asm("mov.b64 %0, {%1, %2};" : "=l"(r) : "f"(lo), "f"(hi)); return r;
}
__device__ __forceinline__ void upk2(u64 v, float& lo, float& hi) {
    asm("mov.b64 {%0, %1}, %2;" : "=f"(lo), "=f"(hi) : "l"(v));
}
__device__ __forceinline__ u64 fma2(u64 a, u64 b, u64 c) {
    u64 d; asm("fma.rn.f32x2 %0, %1, %2, %3;" : "=l"(d) : "l"(a), "l"(b), "l"(c)); return d;
}
__device__ __forceinline__ u64 add2(u64 a, u64 b) {
    u64 d; asm("add.rn.f32x2 %0, %1, %2;" : "=l"(d) : "l"(a), "l"(b)); return d;
}
__device__ __forceinline__ u64 sub2(u64 a, u64 b) {
    u64 d; asm("sub.rn.f32x2 %0, %1, %2;" : "=l"(d) : "l"(a), "l"(b)); return d;
}

// One packed tap = 2 voxel-taps (batch0 lo lane, batch1 hi lane).
// arg --PRMT truncate--> bf16x2 --ex2.bf16x2--> bit-unpack. Only EX2 on MUFU.
__device__ __forceinline__ void tapM(u64 y2, u64 twoyc2, u64 bb2,
                                     u64& num2, u64& den2)
{
    u64 t = sub2(twoyc2, y2);            // 2yc - y
    u64 a = fma2(y2, t, bb2);            // b - (y-yc)^2   (log2 of weight)
    float alo, ahi; upk2(a, alo, ahi);
    u32 abl = __float_as_uint(alo);
    u32 abh = __float_as_uint(ahi);
    u32 h2;
    asm("prmt.b32 %0, %1, %2, 0x7632;" : "=r"(h2) : "r"(abl), "r"(abh)); // bf16x2 truncate-pack
    asm("ex2.approx.ftz.bf16x2 %0, %0;" : "+r"(h2));
    u32 wlo_b = h2 << 16;
    u32 whi_b = h2 & 0xFFFF0000u;
    u64 w2 = pk2(__uint_as_float(wlo_b), __uint_as_float(whi_b));
    num2 = fma2(w2, y2, num2);
    den2 = add2(den2, w2);
}

__global__ __launch_bounds__(NTHREADS, 6)   // 42-reg cap -> 6 CTAs/SM
void bilateral3d_kernel(const float* __restrict__ in,
                        float* __restrict__ out,
                        const float* __restrict__ p_sx,
                        const float* __restrict__ p_sy,
                        const float* __restrict__ p_sz,
                        const float* __restrict__ p_cs)
{
    __shared__ float2 tile[SZT][SYT][SXT];   // 13824 B, holds y = s*x

    const float LOG2E = 1.4426950408889634f;
    const float KB = 1.0f + 1.0f / 512.0f;   // center bf16 truncation bias
    const float sx = *p_sx, sy = *p_sy, sz = *p_sz, cs = *p_cs;
    const float ax = -KB * LOG2E / (2.0f * sx * sx);
    const float ay = -KB * LOG2E / (2.0f * sy * sy);
    const float az = -KB * LOG2E / (2.0f * sz * sz);
    const float s  = sqrtf(KB * LOG2E / (2.0f * cs * cs));

    const int x0 = blockIdx.x * TX;
    const int y0 = blockIdx.y * TY;
    const int z0 = blockIdx.z * TZ;

    // ---- cooperative tile load (pre-scaled by s), sentinel halo ----
    const float BIG = 1e18f;   // OOB: arg ~ -huge -> bf16 -> ex2 -> exact 0
    const int tid = threadIdx.x + TX * (threadIdx.y + TY * threadIdx.z);
    float2* tflat = &tile[0][0][0];
    for (int i = tid; i < SZT*SYT*SXT; i += NTHREADS) {
        int lxx = i % SXT;
        int t   = i / SXT;
        int lyy = t % SYT;
        int lzz = t / SYT;
        int gx = x0 + lxx - R;
        int gy = y0 + lyy - R;
        int gz = z0 + lzz - R;
        float2 v = make_float2(BIG, BIG);
        if ((unsigned)gx < NDIM && (unsigned)gy < NDIM && (unsigned)gz < NDIM) {
            size_t g = ((size_t)gz * NDIM + gy) * NDIM + gx;
            v.x = in[g] * s;
            v.y = in[g + NVOX] * s;
        }
        tflat[i] = v;
    }
    __syncthreads();

    const int lx = threadIdx.x, ly = threadIdx.y, lz = threadIdx.z;
    const float2 yc2 = tile[lz + R][ly + R][lx + R];   // s*xc per lane
    const float ycsq_lo = yc2.x * yc2.x;
    const float ycsq_hi = yc2.y * yc2.y;
    const u64 twoyc2 = pk2(2.0f * yc2.x, 2.0f * yc2.y);
    const u64 yc2pk  = pk2(yc2.x, yc2.y);
    const u64 one2pk = pk2(1.0f, 1.0f);

    u64 num2 = pk2(0.0f, 0.0f);
    u64 den2 = pk2(0.0f, 0.0f);

    #define TAP_M(r_, bb_) tapM(r_, twoyc2, bb_, num2, den2)

    // ---- dz in {0,1,3,4}: rolled ----
    #pragma unroll 1
    for (int izz = 0; izz < 4; izz++) {
        int dz = izz + (izz >> 1);        // {0,1,3,4}
        float dzf = (float)(dz - R);
        float wzv = dzf * dzf * az;
        #pragma unroll
        for (int dy = 0; dy < 5; dy++) {
            float dyf = (float)(dy - R);
            const float b0 = fmaf(dyf * dyf, ay, wzv);
            const float b1 = b0 + ax;
            const float b4 = b0 + 4.0f * ax;
            const u64 bb0 = pk2(b0 - ycsq_lo, b0 - ycsq_hi);
            const u64 bb1 = pk2(b1 - ycsq_lo, b1 - ycsq_hi);
            const u64 bb4 = pk2(b4 - ycsq_lo, b4 - ycsq_hi);
            const u64* row = reinterpret_cast<const u64*>(&tile[lz + dz][ly + dy][lx]);
            u64 r0 = row[0], r1 = row[1], r2 = row[2], r3 = row[3], r4 = row[4];
            TAP_M(r0, bb4);
            TAP_M(r1, bb1);
            TAP_M(r2, bb0);
            TAP_M(r3, bb1);
            TAP_M(r4, bb4);
        }
    }

    // ---- dz == 2 (peeled): center tap is exact w = 1, no EX2 ----
    {
        #pragma unroll
        for (int dy = 0; dy < 5; dy++) {
            float dyf = (float)(dy - R);
            const float b0 = dyf * dyf * ay;
            const float b1 = b0 + ax;
            const float b4 = b0 + 4.0f * ax;
            const u64 bb0 = pk2(b0 - ycsq_lo, b0 - ycsq_hi);
            const u64 bb1 = pk2(b1 - ycsq_lo, b1 - ycsq_hi);
            const u64 bb4 = pk2(b4 - ycsq_lo, b4 - ycsq_hi);
            const u64* row = reinterpret_cast<const u64*>(&tile[lz + 2][ly + dy][lx]);
            u64 r0 = row[0], r1 = row[1], r2 = row[2], r3 = row[3], r4 = row[4];
            TAP_M(r0, bb4);
            TAP_M(r1, bb1);
            if (dy == 2) {
                num2 = add2(num2, yc2pk);     // w = 1 exactly: num += yc
                den2 = add2(den2, one2pk);    //               den += 1
                (void)r2;
            } else {
                TAP_M(r2, bb0);
            }
            TAP_M(r3, bb1);
            TAP_M(r4, bb4);
        }
    }
    #undef TAP_M

    float nlo, nhi, dlo, dhi;
    upk2(num2, nlo, nhi);
    upk2(den2, dlo, dhi);

    const float inv_s = __fdividef(1.0f, s);
    const size_t o = ((size_t)(z0 + lz) * NDIM + (y0 + ly)) * NDIM + (x0 + lx);
    out[o]        = __fdividef(nlo, dlo) * inv_s;
    out[o + NVOX] = __fdividef(nhi, dhi) * inv_s;
}

extern "C" void kernel_launch(void* const* d_in, const int* in_sizes, int n_in,
                              void* d_out, int out_size)
{
    const float* img = (const float*)d_in[0];
    const float* psx = (const float*)d_in[1];
    const float* psy = (const float*)d_in[2];
    const float* psz = (const float*)d_in[3];
    const float* pcs = (const float*)d_in[4];
    float* outp = (float*)d_out;

    dim3 block(TX, TY, TZ);
    dim3 grid(NDIM / TX, NDIM / TY, NDIM / TZ);
    bilateral3d_kernel<<<grid, block>>>(img, outp, psx, psy, psz, pcs);
}